// round 15
// baseline (speedup 1.0000x reference)
#include <cuda_runtime.h>
#include <cuda_bf16.h>
#include <cuda_fp16.h>
#include <cstdint>

#define B_ 16
#define D_ 512
#define N_ 4096
#define K_ 64
#define EPSV 1e-12f

// ---- scratch ----
__device__ __half g_S16[B_ * K_ * N_];     // fp16 softmax weights
__device__ float g_Vp[4 * B_ * K_ * D_];   // GEMM2 partials (n-split 4)
__device__ float g_wsumP[B_ * 32 * K_];    // per-(b, ntile, k) wsum partials
__device__ float g_rn[B_ * K_];

// ============================ helpers ============================
__device__ __forceinline__ uint32_t smem_to_u32(const void* p) {
    uint32_t a;
    asm("{ .reg .u64 t; cvta.to.shared.u64 t, %1; cvt.u32.u64 %0, t; }" : "=r"(a) : "l"(p));
    return a;
}
__device__ __forceinline__ void ldsm4(uint32_t a, uint32_t r[4]) {
    asm volatile("ldmatrix.sync.aligned.m8n8.x4.shared.b16 {%0,%1,%2,%3},[%4];"
                 : "=r"(r[0]), "=r"(r[1]), "=r"(r[2]), "=r"(r[3]) : "r"(a));
}
__device__ __forceinline__ void ldsm4t(uint32_t a, uint32_t r[4]) {
    asm volatile("ldmatrix.sync.aligned.m8n8.x4.trans.shared.b16 {%0,%1,%2,%3},[%4];"
                 : "=r"(r[0]), "=r"(r[1]), "=r"(r[2]), "=r"(r[3]) : "r"(a));
}
__device__ __forceinline__ void mma_bf16(float c[4], const uint32_t a[4],
                                         uint32_t b0, uint32_t b1) {
    asm volatile(
        "mma.sync.aligned.m16n8k16.row.col.f32.bf16.bf16.f32 "
        "{%0,%1,%2,%3},{%4,%5,%6,%7},{%8,%9},{%0,%1,%2,%3};"
        : "+f"(c[0]), "+f"(c[1]), "+f"(c[2]), "+f"(c[3])
        : "r"(a[0]), "r"(a[1]), "r"(a[2]), "r"(a[3]), "r"(b0), "r"(b1));
}
__device__ __forceinline__ void mma_f16(float c[4], const uint32_t a[4],
                                        uint32_t b0, uint32_t b1) {
    asm volatile(
        "mma.sync.aligned.m16n8k16.row.col.f32.f16.f16.f32 "
        "{%0,%1,%2,%3},{%4,%5,%6,%7},{%8,%9},{%0,%1,%2,%3};"
        : "+f"(c[0]), "+f"(c[1]), "+f"(c[2]), "+f"(c[3])
        : "r"(a[0]), "r"(a[1]), "r"(a[2]), "r"(a[3]), "r"(b0), "r"(b1));
}
__device__ __forceinline__ void sts64(uint32_t a, uint32_t r0, uint32_t r1) {
    asm volatile("st.shared.v2.b32 [%0],{%1,%2};" :: "r"(a), "r"(r0), "r"(r1) : "memory");
}
__device__ __forceinline__ void sts128(uint32_t a, uint32_t r0, uint32_t r1,
                                       uint32_t r2, uint32_t r3) {
    asm volatile("st.shared.v4.b32 [%0],{%1,%2,%3,%4};"
                 :: "r"(a), "r"(r0), "r"(r1), "r"(r2), "r"(r3) : "memory");
}
// bf16 hi/lo split (G1): f0,f1 -> hi bf16x2 (f0 low), lo bf16x2 residuals
__device__ __forceinline__ void cvt_hilo(float f0, float f1, uint32_t& h, uint32_t& l) {
    asm("cvt.rn.bf16x2.f32 %0, %1, %2;" : "=r"(h) : "f"(f1), "f"(f0));
    const float fh0 = __uint_as_float(h << 16);
    const float fh1 = __uint_as_float(h & 0xffff0000u);
    asm("cvt.rn.bf16x2.f32 %0, %1, %2;" : "=r"(l) : "f"(f1 - fh1), "f"(f0 - fh0));
}
// single fp16x2 convert (G2 A operand)
__device__ __forceinline__ uint32_t cvt_h2(float f0, float f1) {
    uint32_t h;
    asm("cvt.rn.f16x2.f32 %0, %1, %2;" : "=r"(h) : "f"(f1), "f"(f0));
    return h;
}
__device__ __forceinline__ uint32_t ph16(float f) {
    return (uint32_t)__half_as_ushort(__float2half_rn(f));
}
__device__ __forceinline__ float warp_sum(float v) {
    v += __shfl_xor_sync(0xffffffffu, v, 16);
    v += __shfl_xor_sync(0xffffffffu, v, 8);
    v += __shfl_xor_sync(0xffffffffu, v, 4);
    v += __shfl_xor_sync(0xffffffffu, v, 2);
    v += __shfl_xor_sync(0xffffffffu, v, 1);
    return v;
}

// ============================================================================
// G1: logits = x^T W^T + b (split-bf16, 3 terms) -> softmax over 64 -> fp16 S
//     + per-block wsum partials. Proven structure. UNCHANGED from 92.2us base.
// grid (32, 16), 256 thr. Block: 128 tokens x 64 clusters, K=512 (8 chunks).
// ============================================================================
#define XHI 0
#define XLO 16384
#define WHI 32768
#define WLO 40960
#define BIASOF 49152
#define G1_SMEM 49408

__global__ __launch_bounds__(256, 2) void g1_softmax(
    const float* __restrict__ x, const float* __restrict__ Wc,
    const float* __restrict__ bc) {
    extern __shared__ char smem[];
    const uint32_t sb = smem_to_u32(smem);
    const int t = threadIdx.x, T = t & 31, w = t >> 5;
    const int b = blockIdx.y, n0 = blockIdx.x * 128;
    const float* xb = x + (size_t)b * (D_ * N_);
    if (t < 64) ((float*)(smem + BIASOF))[t] = bc[t];

    float acc[8][4];
#pragma unroll
    for (int j = 0; j < 8; j++)
#pragma unroll
        for (int i = 0; i < 4; i++) acc[j][i] = 0.0f;

    const int ak = ((T >> 4) & 1) * 8 + (T & 7);
    const int am = (w * 16 + ((T >> 3) & 1) * 8) * 2;
    const int bn = ((T >> 4) & 1) * 8 + (T & 7);
    const int bkb = ((T >> 3) & 1) * 16;
    const int wcl = t >> 2;

    for (int c = 0; c < 8; c++) {
        const int d0 = c * 64;
        float4 xv[8];
#pragma unroll
        for (int i = 0; i < 8; i++)
            xv[i] = *(const float4*)(xb + (size_t)(d0 + i * 8 + w) * N_ + n0 + T * 4);
        float4 wv[4];
#pragma unroll
        for (int i = 0; i < 4; i++)
            wv[i] = *(const float4*)(Wc + (size_t)wcl * D_ + d0 + (t & 3) * 4 + i * 16);

        __syncthreads();   // prev chunk's ldmatrix complete
#pragma unroll
        for (int i = 0; i < 8; i++) {
            const int dd = i * 8 + w;
            const uint32_t col = (uint32_t)(T * 8) ^ (uint32_t)((dd & 7) << 4);
            uint32_t h0, l0, h1, l1;
            cvt_hilo(xv[i].x, xv[i].y, h0, l0);
            cvt_hilo(xv[i].z, xv[i].w, h1, l1);
            sts64(sb + XHI + dd * 256 + col, h0, h1);
            sts64(sb + XLO + dd * 256 + col, l0, l1);
        }
#pragma unroll
        for (int i = 0; i < 4; i++) {
            const uint32_t col =
                (uint32_t)((t & 3) * 8 + i * 32) ^ (uint32_t)((wcl & 7) << 4);
            uint32_t h0, l0, h1, l1;
            cvt_hilo(wv[i].x, wv[i].y, h0, l0);
            cvt_hilo(wv[i].z, wv[i].w, h1, l1);
            sts64(sb + WHI + wcl * 128 + col, h0, h1);
            sts64(sb + WLO + wcl * 128 + col, l0, l1);
        }
        __syncthreads();

#pragma unroll
        for (int ks = 0; ks < 4; ks++) {
            const int kd = ks * 16;
            const int arow = kd + ak;
            const uint32_t aaddr =
                sb + XHI + arow * 256 + ((uint32_t)am ^ (uint32_t)((arow & 7) << 4));
            uint32_t ah[4], al[4];
            ldsm4t(aaddr, ah);
            ldsm4t(aaddr + (XLO - XHI), al);
            uint32_t bh[4][4], bl[4][4];
#pragma unroll
            for (int g = 0; g < 4; g++) {
                const int brow = g * 16 + bn;
                const uint32_t baddr = sb + WHI + brow * 128 +
                    ((uint32_t)(kd * 2 + bkb) ^ (uint32_t)((brow & 7) << 4));
                ldsm4(baddr, bh[g]);
                ldsm4(baddr + (WLO - WHI), bl[g]);
            }
#pragma unroll
            for (int g = 0; g < 4; g++) {
                mma_bf16(acc[2 * g], ah, bh[g][0], bh[g][1]);
                mma_bf16(acc[2 * g + 1], ah, bh[g][2], bh[g][3]);
            }
#pragma unroll
            for (int g = 0; g < 4; g++) {
                mma_bf16(acc[2 * g], ah, bl[g][0], bl[g][1]);
                mma_bf16(acc[2 * g + 1], ah, bl[g][2], bl[g][3]);
            }
#pragma unroll
            for (int g = 0; g < 4; g++) {
                mma_bf16(acc[2 * g], al, bh[g][0], bh[g][1]);
                mma_bf16(acc[2 * g + 1], al, bh[g][2], bh[g][3]);
            }
        }
    }
    __syncthreads();

    // bias + softmax (rows r0 = w*16 + T/4, r1 = r0+8; quad holds full 64 cl)
    const float* bias = (const float*)(smem + BIASOF);
    float m0 = -3.0e38f, m1 = -3.0e38f;
#pragma unroll
    for (int j = 0; j < 8; j++) {
        const float bb0 = bias[j * 8 + (T & 3) * 2];
        const float bb1 = bias[j * 8 + (T & 3) * 2 + 1];
        acc[j][0] += bb0; acc[j][1] += bb1;
        acc[j][2] += bb0; acc[j][3] += bb1;
        m0 = fmaxf(m0, fmaxf(acc[j][0], acc[j][1]));
        m1 = fmaxf(m1, fmaxf(acc[j][2], acc[j][3]));
    }
    m0 = fmaxf(m0, __shfl_xor_sync(0xffffffffu, m0, 1));
    m0 = fmaxf(m0, __shfl_xor_sync(0xffffffffu, m0, 2));
    m1 = fmaxf(m1, __shfl_xor_sync(0xffffffffu, m1, 1));
    m1 = fmaxf(m1, __shfl_xor_sync(0xffffffffu, m1, 2));
    float s0 = 0.0f, s1 = 0.0f;
#pragma unroll
    for (int j = 0; j < 8; j++) {
        acc[j][0] = __expf(acc[j][0] - m0); s0 += acc[j][0];
        acc[j][1] = __expf(acc[j][1] - m0); s0 += acc[j][1];
        acc[j][2] = __expf(acc[j][2] - m1); s1 += acc[j][2];
        acc[j][3] = __expf(acc[j][3] - m1); s1 += acc[j][3];
    }
    s0 += __shfl_xor_sync(0xffffffffu, s0, 1);
    s0 += __shfl_xor_sync(0xffffffffu, s0, 2);
    s1 += __shfl_xor_sync(0xffffffffu, s1, 1);
    s1 += __shfl_xor_sync(0xffffffffu, s1, 2);
    const float inv0 = 1.0f / s0, inv1 = 1.0f / s1;

    uint32_t* Ts = (uint32_t*)smem;   // [64][132] padded, fp16 in low 16 bits
    const int tok0 = w * 16 + (T >> 2), tok1 = tok0 + 8;
#pragma unroll
    for (int j = 0; j < 8; j++) {
        const int cl = j * 8 + (T & 3) * 2;
        Ts[cl * 132 + tok0] = ph16(acc[j][0] * inv0);
        Ts[(cl + 1) * 132 + tok0] = ph16(acc[j][1] * inv0);
        Ts[cl * 132 + tok1] = ph16(acc[j][2] * inv1);
        Ts[(cl + 1) * 132 + tok1] = ph16(acc[j][3] * inv1);
    }
    __syncthreads();
    // store fp16 S (each of 4 threads per cl: 32 contiguous tokens) + wsum
    const int cl = t >> 2, pp = t & 3;
    const uint32_t* Tr = Ts + cl * 132 + pp * 32;
    float wacc = 0.0f;
    uint32_t ov[16];
#pragma unroll
    for (int j = 0; j < 16; j++) {
        const uint32_t a0 = Tr[2 * j], a1 = Tr[2 * j + 1];
        ov[j] = (a0 & 0xffffu) | (a1 << 16);
        wacc += __half2float(__ushort_as_half((unsigned short)a0));
        wacc += __half2float(__ushort_as_half((unsigned short)a1));
    }
    uint32_t* SgU = (uint32_t*)(g_S16 + (size_t)(b * 64 + cl) * N_ + n0 + pp * 32);
#pragma unroll
    for (int j = 0; j < 4; j++)
        *(uint4*)(SgU + 4 * j) =
            make_uint4(ov[4 * j], ov[4 * j + 1], ov[4 * j + 2], ov[4 * j + 3]);
    wacc += __shfl_xor_sync(0xffffffffu, wacc, 1);
    wacc += __shfl_xor_sync(0xffffffffu, wacc, 2);
    if (pp == 0)
        g_wsumP[((size_t)b * 32 + blockIdx.x) * K_ + cl] = wacc;
}

// ============================================================================
// G2: V[d,k] = sum_n x[d,n] * S[n,k]  (fp16 single term). n-chunk 128.
// grid (4 dtile, 16 b, 4 nsplit), 256 thr. Block: 128 d x 64 cl, K=1024 n.
// smem: A fp16 [128d][128n] 32KB + S fp16 [64k][128n] 16KB = 48KB; 2 CTAs/SM.
// 8 iterations (half the syncs of chunk-64), 64 MMAs per sync window.
// Accumulation order over n identical to chunk-64 -> bitwise same result.
// ============================================================================
#define AHI 0
#define BOF 32768
#define G2_SMEM 49152

__global__ __launch_bounds__(256, 2) void g2_wx(const float* __restrict__ x) {
    extern __shared__ char smem[];
    const uint32_t sb = smem_to_u32(smem);
    const int t = threadIdx.x, T = t & 31, w = t >> 5;
    const int d0 = blockIdx.x * 128, b = blockIdx.y, ns = blockIdx.z;
    const float* xb = x + (size_t)b * (D_ * N_);
    const __half* Sb = g_S16 + (size_t)b * (K_ * N_);

    float acc[8][4];
#pragma unroll
    for (int j = 0; j < 8; j++)
#pragma unroll
        for (int i = 0; i < 4; i++) acc[j][i] = 0.0f;

    const int am8 = ((T >> 3) & 1) * 8;
    const int akb = ((T >> 4) & 1) * 16;
    const int bn = ((T >> 4) & 1) * 8 + (T & 7);
    const int bkb = ((T >> 3) & 1) * 16;
    const int scl = t >> 2;

    for (int ch = 0; ch < 8; ch++) {
        const int nb = ns * 1024 + ch * 128;
        // batch0 x loads (d rows 0..63) + S loads
        float4 xv[8];
#pragma unroll
        for (int i = 0; i < 8; i++) {
            const int flat = i * 1024 + t * 4;
            xv[i] = *(const float4*)(xb + (size_t)(d0 + (flat >> 7)) * N_ +
                                     nb + (flat & 127));
        }
        uint4 sv[4];
#pragma unroll
        for (int i = 0; i < 4; i++)
            sv[i] = *(const uint4*)(Sb + (size_t)scl * N_ + nb + (t & 3) * 32 + i * 8);

        __syncthreads();   // prev chunk's ldmatrix complete
#pragma unroll
        for (int i = 0; i < 8; i++) {
            const int flat = i * 1024 + t * 4;
            const int dd = flat >> 7, nn = flat & 127;
            const uint32_t col = (uint32_t)(nn * 2) ^ (uint32_t)((dd & 7) << 4);
            sts64(sb + AHI + dd * 256 + col,
                  cvt_h2(xv[i].x, xv[i].y), cvt_h2(xv[i].z, xv[i].w));
        }
        // batch1 x loads (d rows 64..127)
#pragma unroll
        for (int i = 0; i < 8; i++) {
            const int flat = i * 1024 + t * 4;
            xv[i] = *(const float4*)(xb + (size_t)(d0 + 64 + (flat >> 7)) * N_ +
                                     nb + (flat & 127));
        }
#pragma unroll
        for (int i = 0; i < 8; i++) {
            const int flat = i * 1024 + t * 4;
            const int dd = 64 + (flat >> 7), nn = flat & 127;
            const uint32_t col = (uint32_t)(nn * 2) ^ (uint32_t)((dd & 7) << 4);
            sts64(sb + AHI + dd * 256 + col,
                  cvt_h2(xv[i].x, xv[i].y), cvt_h2(xv[i].z, xv[i].w));
        }
        // S tile stores (row = scl, 64B per thread)
#pragma unroll
        for (int i = 0; i < 4; i++) {
            const uint32_t col =
                (uint32_t)((t & 3) * 64 + i * 16) ^ (uint32_t)((scl & 7) << 4);
            sts128(sb + BOF + scl * 256 + col, sv[i].x, sv[i].y, sv[i].z, sv[i].w);
        }
        __syncthreads();

#pragma unroll
        for (int ks = 0; ks < 8; ks++) {
            const int kd = ks * 16;
            const int arow = w * 16 + am8 + (T & 7);
            const uint32_t aaddr = sb + AHI + arow * 256 +
                ((uint32_t)(kd * 2 + akb) ^ (uint32_t)((arow & 7) << 4));
            uint32_t ah[4];
            ldsm4(aaddr, ah);
            uint32_t bs[4][4];
#pragma unroll
            for (int g = 0; g < 4; g++) {
                const int brow = g * 16 + bn;
                const uint32_t baddr = sb + BOF + brow * 256 +
                    ((uint32_t)(kd * 2 + bkb) ^ (uint32_t)((brow & 7) << 4));
                ldsm4(baddr, bs[g]);
            }
#pragma unroll
            for (int g = 0; g < 4; g++) {
                mma_f16(acc[2 * g], ah, bs[g][0], bs[g][1]);
                mma_f16(acc[2 * g + 1], ah, bs[g][2], bs[g][3]);
            }
        }
    }
    __syncthreads();

    // smem transpose -> coalesced [k][d] stores
    float* Vt = (float*)smem;   // [64][132] padded
    const int dd0 = w * 16 + (T >> 2), dd1 = dd0 + 8;
#pragma unroll
    for (int j = 0; j < 8; j++) {
        const int cl = j * 8 + (T & 3) * 2;
        Vt[cl * 132 + dd0] = acc[j][0];
        Vt[(cl + 1) * 132 + dd0] = acc[j][1];
        Vt[cl * 132 + dd1] = acc[j][2];
        Vt[(cl + 1) * 132 + dd1] = acc[j][3];
    }
    __syncthreads();
    float* Vp = g_Vp + (size_t)ns * (B_ * K_ * D_);
    const int cl = t >> 2;
    float* dst = Vp + (size_t)(b * 64 + cl) * D_ + d0;
#pragma unroll
    for (int jj = 0; jj < 8; jj++) {
        const int colx = (t & 3) * 4 + jj * 16;
        float4 v;
        v.x = Vt[cl * 132 + colx];     v.y = Vt[cl * 132 + colx + 1];
        v.z = Vt[cl * 132 + colx + 2]; v.w = Vt[cl * 132 + colx + 3];
        *(float4*)(dst + colx) = v;
    }
}

// ============================================================================
// norm1: vlad = sum(4 partials) - wsum*c, intra-L2-normalize, emit norm^2.
// ============================================================================
__global__ __launch_bounds__(128) void k_norm1(
    const float* __restrict__ centers, float* __restrict__ out) {
    const int k = blockIdx.x, b = blockIdx.y, t = threadIdx.x;
    const size_t row = ((size_t)b * K_ + k) * D_;
    __shared__ float wsh;
    if (t < 32) {
        float p = g_wsumP[((size_t)b * 32 + t) * K_ + k];
        p = warp_sum(p);
        if (t == 0) wsh = p;
    }
    const float4 v0 = *(const float4*)(g_Vp + row + t * 4);
    const float4 v1 = *(const float4*)(g_Vp + (size_t)(B_ * K_ * D_) + row + t * 4);
    const float4 v2 = *(const float4*)(g_Vp + (size_t)2 * (B_ * K_ * D_) + row + t * 4);
    const float4 v3 = *(const float4*)(g_Vp + (size_t)3 * (B_ * K_ * D_) + row + t * 4);
    const float4 c = *(const float4*)(centers + k * D_ + t * 4);
    __syncthreads();
    const float ws = wsh;
    float4 val;
    val.x = ((v0.x + v1.x) + (v2.x + v3.x)) - ws * c.x;
    val.y = ((v0.y + v1.y) + (v2.y + v3.y)) - ws * c.y;
    val.z = ((v0.z + v1.z) + (v2.z + v3.z)) - ws * c.z;
    val.w = ((v0.w + v1.w) + (v2.w + v3.w)) - ws * c.w;
    float ss = val.x * val.x + val.y * val.y + val.z * val.z + val.w * val.w;
    ss = warp_sum(ss);
    __shared__ float sm[4];
    if ((t & 31) == 0) sm[t >> 5] = ss;
    __syncthreads();
    const float total = (sm[0] + sm[1]) + (sm[2] + sm[3]);
    const float inv = 1.0f / fmaxf(sqrtf(total), EPSV);
    val.x *= inv; val.y *= inv; val.z *= inv; val.w *= inv;
    *(float4*)(out + row + t * 4) = val;
    if (t == 0) g_rn[b * K_ + k] = total * inv * inv;
}

// ============================================================================
// scale: global L2 with inline per-block rnsum; 2 float4 per thread.
// Grid 256 (16 blocks per batch), 256 threads.
// ============================================================================
__global__ __launch_bounds__(256) void k_scale(float* __restrict__ out) {
    const int t = threadIdx.x;
    const int b = blockIdx.x >> 4;               // 16 blocks per batch
    __shared__ float sm2[2];
    __shared__ float invs;
    if (t < 64) {
        float v = g_rn[b * K_ + t];
        v += __shfl_xor_sync(0xffffffffu, v, 16);
        v += __shfl_xor_sync(0xffffffffu, v, 8);
        v += __shfl_xor_sync(0xffffffffu, v, 4);
        v += __shfl_xor_sync(0xffffffffu, v, 2);
        v += __shfl_xor_sync(0xffffffffu, v, 1);
        if ((t & 31) == 0) sm2[t >> 5] = v;
    }
    const size_t gi0 = (size_t)blockIdx.x * 2048 + t * 4;
    float4 v0 = *(float4*)(out + gi0);
    float4 v1 = *(float4*)(out + gi0 + 1024);
    __syncthreads();
    if (t == 0) invs = 1.0f / fmaxf(sqrtf(sm2[0] + sm2[1]), EPSV);
    __syncthreads();
    const float inv = invs;
    v0.x *= inv; v0.y *= inv; v0.z *= inv; v0.w *= inv;
    v1.x *= inv; v1.y *= inv; v1.z *= inv; v1.w *= inv;
    *(float4*)(out + gi0) = v0;
    *(float4*)(out + gi0 + 1024) = v1;
}

// ============================================================================
extern "C" void kernel_launch(void* const* d_in, const int* in_sizes, int n_in,
                              void* d_out, int out_size) {
    const float* x = (const float*)d_in[0];
    const float* conv_w = (const float*)d_in[1];
    const float* conv_b = (const float*)d_in[2];
    const float* centers = (const float*)d_in[3];
    float* out = (float*)d_out;

    cudaFuncSetAttribute(g1_softmax, cudaFuncAttributeMaxDynamicSharedMemorySize, G1_SMEM);
    cudaFuncSetAttribute(g2_wx, cudaFuncAttributeMaxDynamicSharedMemorySize, G2_SMEM);

    g1_softmax<<<dim3(32, 16), 256, G1_SMEM>>>(x, conv_w, conv_b);
    g2_wx<<<dim3(4, 16, 4), 256, G2_SMEM>>>(x);
    k_norm1<<<dim3(64, 16), 128>>>(centers, out);
    k_scale<<<256, 256>>>(out);
}

// round 17
// speedup vs baseline: 1.0456x; 1.0456x over previous
#include <cuda_runtime.h>
#include <cuda_bf16.h>
#include <cuda_fp16.h>
#include <cstdint>

#define B_ 16
#define D_ 512
#define N_ 4096
#define K_ 64
#define EPSV 1e-12f

// ---- scratch ----
__device__ __half g_S16[B_ * K_ * N_];     // fp16 softmax weights
__device__ float g_Vp[4 * B_ * K_ * D_];   // GEMM2 partials (n-split 4)
__device__ float g_wsumP[B_ * 32 * K_];    // per-(b, ntile, k) wsum partials
__device__ float g_rn[B_ * K_];

// ============================ helpers ============================
__device__ __forceinline__ uint32_t smem_to_u32(const void* p) {
    uint32_t a;
    asm("{ .reg .u64 t; cvta.to.shared.u64 t, %1; cvt.u32.u64 %0, t; }" : "=r"(a) : "l"(p));
    return a;
}
__device__ __forceinline__ void ldsm4(uint32_t a, uint32_t r[4]) {
    asm volatile("ldmatrix.sync.aligned.m8n8.x4.shared.b16 {%0,%1,%2,%3},[%4];"
                 : "=r"(r[0]), "=r"(r[1]), "=r"(r[2]), "=r"(r[3]) : "r"(a));
}
__device__ __forceinline__ void ldsm4t(uint32_t a, uint32_t r[4]) {
    asm volatile("ldmatrix.sync.aligned.m8n8.x4.trans.shared.b16 {%0,%1,%2,%3},[%4];"
                 : "=r"(r[0]), "=r"(r[1]), "=r"(r[2]), "=r"(r[3]) : "r"(a));
}
__device__ __forceinline__ void mma_bf16(float c[4], const uint32_t a[4],
                                         uint32_t b0, uint32_t b1) {
    asm volatile(
        "mma.sync.aligned.m16n8k16.row.col.f32.bf16.bf16.f32 "
        "{%0,%1,%2,%3},{%4,%5,%6,%7},{%8,%9},{%0,%1,%2,%3};"
        : "+f"(c[0]), "+f"(c[1]), "+f"(c[2]), "+f"(c[3])
        : "r"(a[0]), "r"(a[1]), "r"(a[2]), "r"(a[3]), "r"(b0), "r"(b1));
}
__device__ __forceinline__ void mma_f16(float c[4], const uint32_t a[4],
                                        uint32_t b0, uint32_t b1) {
    asm volatile(
        "mma.sync.aligned.m16n8k16.row.col.f32.f16.f16.f32 "
        "{%0,%1,%2,%3},{%4,%5,%6,%7},{%8,%9},{%0,%1,%2,%3};"
        : "+f"(c[0]), "+f"(c[1]), "+f"(c[2]), "+f"(c[3])
        : "r"(a[0]), "r"(a[1]), "r"(a[2]), "r"(a[3]), "r"(b0), "r"(b1));
}
__device__ __forceinline__ void sts64(uint32_t a, uint32_t r0, uint32_t r1) {
    asm volatile("st.shared.v2.b32 [%0],{%1,%2};" :: "r"(a), "r"(r0), "r"(r1) : "memory");
}
__device__ __forceinline__ void sts128(uint32_t a, uint32_t r0, uint32_t r1,
                                       uint32_t r2, uint32_t r3) {
    asm volatile("st.shared.v4.b32 [%0],{%1,%2,%3,%4};"
                 :: "r"(a), "r"(r0), "r"(r1), "r"(r2), "r"(r3) : "memory");
}
// bf16 hi/lo split (G1): f0,f1 -> hi bf16x2 (f0 low), lo bf16x2 residuals
__device__ __forceinline__ void cvt_hilo(float f0, float f1, uint32_t& h, uint32_t& l) {
    asm("cvt.rn.bf16x2.f32 %0, %1, %2;" : "=r"(h) : "f"(f1), "f"(f0));
    const float fh0 = __uint_as_float(h << 16);
    const float fh1 = __uint_as_float(h & 0xffff0000u);
    asm("cvt.rn.bf16x2.f32 %0, %1, %2;" : "=r"(l) : "f"(f1 - fh1), "f"(f0 - fh0));
}
// single fp16x2 convert (G2 A operand)
__device__ __forceinline__ uint32_t cvt_h2(float f0, float f1) {
    uint32_t h;
    asm("cvt.rn.f16x2.f32 %0, %1, %2;" : "=r"(h) : "f"(f1), "f"(f0));
    return h;
}
__device__ __forceinline__ uint32_t ph16(float f) {
    return (uint32_t)__half_as_ushort(__float2half_rn(f));
}
__device__ __forceinline__ float warp_sum(float v) {
    v += __shfl_xor_sync(0xffffffffu, v, 16);
    v += __shfl_xor_sync(0xffffffffu, v, 8);
    v += __shfl_xor_sync(0xffffffffu, v, 4);
    v += __shfl_xor_sync(0xffffffffu, v, 2);
    v += __shfl_xor_sync(0xffffffffu, v, 1);
    return v;
}

// ============================================================================
// G1: logits = x^T W^T + b (split-bf16, 3 terms) -> softmax over 64 -> fp16 S
//     + per-block wsum partials. UNCHANGED from verified 92.2us base.
// grid (32, 16), 256 thr. Block: 128 tokens x 64 clusters, K=512 (8 chunks).
// ============================================================================
#define XHI 0
#define XLO 16384
#define WHI 32768
#define WLO 40960
#define BIASOF 49152
#define G1_SMEM 49408

__global__ __launch_bounds__(256, 2) void g1_softmax(
    const float* __restrict__ x, const float* __restrict__ Wc,
    const float* __restrict__ bc) {
    extern __shared__ char smem[];
    const uint32_t sb = smem_to_u32(smem);
    const int t = threadIdx.x, T = t & 31, w = t >> 5;
    const int b = blockIdx.y, n0 = blockIdx.x * 128;
    const float* xb = x + (size_t)b * (D_ * N_);
    if (t < 64) ((float*)(smem + BIASOF))[t] = bc[t];

    float acc[8][4];
#pragma unroll
    for (int j = 0; j < 8; j++)
#pragma unroll
        for (int i = 0; i < 4; i++) acc[j][i] = 0.0f;

    const int ak = ((T >> 4) & 1) * 8 + (T & 7);
    const int am = (w * 16 + ((T >> 3) & 1) * 8) * 2;
    const int bn = ((T >> 4) & 1) * 8 + (T & 7);
    const int bkb = ((T >> 3) & 1) * 16;
    const int wcl = t >> 2;

    for (int c = 0; c < 8; c++) {
        const int d0 = c * 64;
        float4 xv[8];
#pragma unroll
        for (int i = 0; i < 8; i++)
            xv[i] = *(const float4*)(xb + (size_t)(d0 + i * 8 + w) * N_ + n0 + T * 4);
        float4 wv[4];
#pragma unroll
        for (int i = 0; i < 4; i++)
            wv[i] = *(const float4*)(Wc + (size_t)wcl * D_ + d0 + (t & 3) * 4 + i * 16);

        __syncthreads();   // prev chunk's ldmatrix complete
#pragma unroll
        for (int i = 0; i < 8; i++) {
            const int dd = i * 8 + w;
            const uint32_t col = (uint32_t)(T * 8) ^ (uint32_t)((dd & 7) << 4);
            uint32_t h0, l0, h1, l1;
            cvt_hilo(xv[i].x, xv[i].y, h0, l0);
            cvt_hilo(xv[i].z, xv[i].w, h1, l1);
            sts64(sb + XHI + dd * 256 + col, h0, h1);
            sts64(sb + XLO + dd * 256 + col, l0, l1);
        }
#pragma unroll
        for (int i = 0; i < 4; i++) {
            const uint32_t col =
                (uint32_t)((t & 3) * 8 + i * 32) ^ (uint32_t)((wcl & 7) << 4);
            uint32_t h0, l0, h1, l1;
            cvt_hilo(wv[i].x, wv[i].y, h0, l0);
            cvt_hilo(wv[i].z, wv[i].w, h1, l1);
            sts64(sb + WHI + wcl * 128 + col, h0, h1);
            sts64(sb + WLO + wcl * 128 + col, l0, l1);
        }
        __syncthreads();

#pragma unroll
        for (int ks = 0; ks < 4; ks++) {
            const int kd = ks * 16;
            const int arow = kd + ak;
            const uint32_t aaddr =
                sb + XHI + arow * 256 + ((uint32_t)am ^ (uint32_t)((arow & 7) << 4));
            uint32_t ah[4], al[4];
            ldsm4t(aaddr, ah);
            ldsm4t(aaddr + (XLO - XHI), al);
            uint32_t bh[4][4], bl[4][4];
#pragma unroll
            for (int g = 0; g < 4; g++) {
                const int brow = g * 16 + bn;
                const uint32_t baddr = sb + WHI + brow * 128 +
                    ((uint32_t)(kd * 2 + bkb) ^ (uint32_t)((brow & 7) << 4));
                ldsm4(baddr, bh[g]);
                ldsm4(baddr + (WLO - WHI), bl[g]);
            }
#pragma unroll
            for (int g = 0; g < 4; g++) {
                mma_bf16(acc[2 * g], ah, bh[g][0], bh[g][1]);
                mma_bf16(acc[2 * g + 1], ah, bh[g][2], bh[g][3]);
            }
#pragma unroll
            for (int g = 0; g < 4; g++) {
                mma_bf16(acc[2 * g], ah, bl[g][0], bl[g][1]);
                mma_bf16(acc[2 * g + 1], ah, bl[g][2], bl[g][3]);
            }
#pragma unroll
            for (int g = 0; g < 4; g++) {
                mma_bf16(acc[2 * g], al, bh[g][0], bh[g][1]);
                mma_bf16(acc[2 * g + 1], al, bh[g][2], bh[g][3]);
            }
        }
    }
    __syncthreads();

    // bias + softmax (rows r0 = w*16 + T/4, r1 = r0+8; quad holds full 64 cl)
    const float* bias = (const float*)(smem + BIASOF);
    float m0 = -3.0e38f, m1 = -3.0e38f;
#pragma unroll
    for (int j = 0; j < 8; j++) {
        const float bb0 = bias[j * 8 + (T & 3) * 2];
        const float bb1 = bias[j * 8 + (T & 3) * 2 + 1];
        acc[j][0] += bb0; acc[j][1] += bb1;
        acc[j][2] += bb0; acc[j][3] += bb1;
        m0 = fmaxf(m0, fmaxf(acc[j][0], acc[j][1]));
        m1 = fmaxf(m1, fmaxf(acc[j][2], acc[j][3]));
    }
    m0 = fmaxf(m0, __shfl_xor_sync(0xffffffffu, m0, 1));
    m0 = fmaxf(m0, __shfl_xor_sync(0xffffffffu, m0, 2));
    m1 = fmaxf(m1, __shfl_xor_sync(0xffffffffu, m1, 1));
    m1 = fmaxf(m1, __shfl_xor_sync(0xffffffffu, m1, 2));
    float s0 = 0.0f, s1 = 0.0f;
#pragma unroll
    for (int j = 0; j < 8; j++) {
        acc[j][0] = __expf(acc[j][0] - m0); s0 += acc[j][0];
        acc[j][1] = __expf(acc[j][1] - m0); s0 += acc[j][1];
        acc[j][2] = __expf(acc[j][2] - m1); s1 += acc[j][2];
        acc[j][3] = __expf(acc[j][3] - m1); s1 += acc[j][3];
    }
    s0 += __shfl_xor_sync(0xffffffffu, s0, 1);
    s0 += __shfl_xor_sync(0xffffffffu, s0, 2);
    s1 += __shfl_xor_sync(0xffffffffu, s1, 1);
    s1 += __shfl_xor_sync(0xffffffffu, s1, 2);
    const float inv0 = 1.0f / s0, inv1 = 1.0f / s1;

    uint32_t* Ts = (uint32_t*)smem;   // [64][132] padded, fp16 in low 16 bits
    const int tok0 = w * 16 + (T >> 2), tok1 = tok0 + 8;
#pragma unroll
    for (int j = 0; j < 8; j++) {
        const int cl = j * 8 + (T & 3) * 2;
        Ts[cl * 132 + tok0] = ph16(acc[j][0] * inv0);
        Ts[(cl + 1) * 132 + tok0] = ph16(acc[j][1] * inv0);
        Ts[cl * 132 + tok1] = ph16(acc[j][2] * inv1);
        Ts[(cl + 1) * 132 + tok1] = ph16(acc[j][3] * inv1);
    }
    __syncthreads();
    // store fp16 S (each of 4 threads per cl: 32 contiguous tokens) + wsum
    const int cl = t >> 2, pp = t & 3;
    const uint32_t* Tr = Ts + cl * 132 + pp * 32;
    float wacc = 0.0f;
    uint32_t ov[16];
#pragma unroll
    for (int j = 0; j < 16; j++) {
        const uint32_t a0 = Tr[2 * j], a1 = Tr[2 * j + 1];
        ov[j] = (a0 & 0xffffu) | (a1 << 16);
        wacc += __half2float(__ushort_as_half((unsigned short)a0));
        wacc += __half2float(__ushort_as_half((unsigned short)a1));
    }
    uint32_t* SgU = (uint32_t*)(g_S16 + (size_t)(b * 64 + cl) * N_ + n0 + pp * 32);
#pragma unroll
    for (int j = 0; j < 4; j++)
        *(uint4*)(SgU + 4 * j) =
            make_uint4(ov[4 * j], ov[4 * j + 1], ov[4 * j + 2], ov[4 * j + 3]);
    wacc += __shfl_xor_sync(0xffffffffu, wacc, 1);
    wacc += __shfl_xor_sync(0xffffffffu, wacc, 2);
    if (pp == 0)
        g_wsumP[((size_t)b * 32 + blockIdx.x) * K_ + cl] = wacc;
}

// ============================================================================
// G2: V[d,k] = sum_n x[d,n] * S[n,k]  (fp16 single term). EXACT R14 (92.2us).
// grid (4 dtile, 16 b, 4 nsplit), 256 thr. Block: 128 d x 64 cl, K=1024 n.
// smem: A fp16 16KB + S fp16 8KB; chunk 64, 2 CTAs/SM.
// ============================================================================
#define AHI 0
#define BOF 16384
#define G2_SMEM 34048

__global__ __launch_bounds__(256, 2) void g2_wx(const float* __restrict__ x) {
    extern __shared__ char smem[];
    const uint32_t sb = smem_to_u32(smem);
    const int t = threadIdx.x, T = t & 31, w = t >> 5;
    const int d0 = blockIdx.x * 128, b = blockIdx.y, ns = blockIdx.z;
    const float* xb = x + (size_t)b * (D_ * N_);
    const __half* Sb = g_S16 + (size_t)b * (K_ * N_);

    float acc[8][4];
#pragma unroll
    for (int j = 0; j < 8; j++)
#pragma unroll
        for (int i = 0; i < 4; i++) acc[j][i] = 0.0f;

    const int am8 = ((T >> 3) & 1) * 8;
    const int akb = ((T >> 4) & 1) * 16;
    const int bn = ((T >> 4) & 1) * 8 + (T & 7);
    const int bkb = ((T >> 3) & 1) * 16;
    const int scl = t >> 2;

    for (int ch = 0; ch < 16; ch++) {
        const int nb = ns * 1024 + ch * 64;
        float4 xv[8];
#pragma unroll
        for (int i = 0; i < 8; i++)
            xv[i] = *(const float4*)(xb + (size_t)(d0 + i * 16 + (t >> 4)) * N_ +
                                     nb + (t & 15) * 4);
        uint4 sv0 = *(const uint4*)(Sb + (size_t)scl * N_ + nb + (t & 3) * 16);
        uint4 sv1 = *(const uint4*)(Sb + (size_t)scl * N_ + nb + (t & 3) * 16 + 8);

        __syncthreads();
#pragma unroll
        for (int i = 0; i < 8; i++) {
            const int dd = i * 16 + (t >> 4);
            const uint32_t col = (uint32_t)((t & 15) * 8) ^ (uint32_t)((dd & 7) << 4);
            const uint32_t h0 = cvt_h2(xv[i].x, xv[i].y);
            const uint32_t h1 = cvt_h2(xv[i].z, xv[i].w);
            sts64(sb + AHI + dd * 128 + col, h0, h1);
        }
        {   // S tile: raw fp16, two 16B chunks per thread
            const uint32_t c0 = (uint32_t)((t & 3) * 32) ^ (uint32_t)((scl & 7) << 4);
            const uint32_t c1 = (uint32_t)((t & 3) * 32 + 16) ^ (uint32_t)((scl & 7) << 4);
            sts128(sb + BOF + scl * 128 + c0, sv0.x, sv0.y, sv0.z, sv0.w);
            sts128(sb + BOF + scl * 128 + c1, sv1.x, sv1.y, sv1.z, sv1.w);
        }
        __syncthreads();

#pragma unroll
        for (int ks = 0; ks < 4; ks++) {
            const int kd = ks * 16;
            const int arow = w * 16 + am8 + (T & 7);
            const uint32_t aaddr = sb + AHI + arow * 128 +
                ((uint32_t)(kd * 2 + akb) ^ (uint32_t)((arow & 7) << 4));
            uint32_t ah[4];
            ldsm4(aaddr, ah);
            uint32_t bs[4][4];
#pragma unroll
            for (int g = 0; g < 4; g++) {
                const int brow = g * 16 + bn;
                const uint32_t baddr = sb + BOF + brow * 128 +
                    ((uint32_t)(kd * 2 + bkb) ^ (uint32_t)((brow & 7) << 4));
                ldsm4(baddr, bs[g]);
            }
#pragma unroll
            for (int g = 0; g < 4; g++) {
                mma_f16(acc[2 * g], ah, bs[g][0], bs[g][1]);
                mma_f16(acc[2 * g + 1], ah, bs[g][2], bs[g][3]);
            }
        }
    }
    __syncthreads();

    // smem transpose -> coalesced [k][d] stores
    float* Vt = (float*)smem;   // [64][132] padded
    const int dd0 = w * 16 + (T >> 2), dd1 = dd0 + 8;
#pragma unroll
    for (int j = 0; j < 8; j++) {
        const int cl = j * 8 + (T & 3) * 2;
        Vt[cl * 132 + dd0] = acc[j][0];
        Vt[(cl + 1) * 132 + dd0] = acc[j][1];
        Vt[cl * 132 + dd1] = acc[j][2];
        Vt[(cl + 1) * 132 + dd1] = acc[j][3];
    }
    __syncthreads();
    float* Vp = g_Vp + (size_t)ns * (B_ * K_ * D_);
    const int cl = t >> 2;
    float* dst = Vp + (size_t)(b * 64 + cl) * D_ + d0;
#pragma unroll
    for (int jj = 0; jj < 8; jj++) {
        const int colx = (t & 3) * 4 + jj * 16;
        float4 v;
        v.x = Vt[cl * 132 + colx];     v.y = Vt[cl * 132 + colx + 1];
        v.z = Vt[cl * 132 + colx + 2]; v.w = Vt[cl * 132 + colx + 3];
        *(float4*)(dst + colx) = v;
    }
}

// ============================================================================
// norm1: TWO rows (k0, k0+1) per block for doubled MLP. grid (32, 16), 128 thr.
// Same per-row reduction trees as before -> bitwise identical output.
// ============================================================================
__global__ __launch_bounds__(128) void k_norm1(
    const float* __restrict__ centers, float* __restrict__ out) {
    const int k0 = blockIdx.x * 2, b = blockIdx.y, t = threadIdx.x;
    const size_t row0 = ((size_t)b * K_ + k0) * D_;
    const size_t row1 = row0 + D_;
    __shared__ float wsh[2];
    if (t < 64) {
        const int kk = t >> 5, lane = t & 31;
        float p = g_wsumP[((size_t)b * 32 + lane) * K_ + k0 + kk];
        p = warp_sum(p);
        if (lane == 0) wsh[kk] = p;
    }
    const size_t PS = (size_t)(B_ * K_ * D_);
    const float4 a0 = *(const float4*)(g_Vp + row0 + t * 4);
    const float4 a1 = *(const float4*)(g_Vp + PS + row0 + t * 4);
    const float4 a2 = *(const float4*)(g_Vp + 2 * PS + row0 + t * 4);
    const float4 a3 = *(const float4*)(g_Vp + 3 * PS + row0 + t * 4);
    const float4 e0 = *(const float4*)(g_Vp + row1 + t * 4);
    const float4 e1 = *(const float4*)(g_Vp + PS + row1 + t * 4);
    const float4 e2 = *(const float4*)(g_Vp + 2 * PS + row1 + t * 4);
    const float4 e3 = *(const float4*)(g_Vp + 3 * PS + row1 + t * 4);
    const float4 c0 = *(const float4*)(centers + k0 * D_ + t * 4);
    const float4 c1 = *(const float4*)(centers + (k0 + 1) * D_ + t * 4);
    __syncthreads();
    const float ws0 = wsh[0], ws1 = wsh[1];
    float4 v0, v1;
    v0.x = ((a0.x + a1.x) + (a2.x + a3.x)) - ws0 * c0.x;
    v0.y = ((a0.y + a1.y) + (a2.y + a3.y)) - ws0 * c0.y;
    v0.z = ((a0.z + a1.z) + (a2.z + a3.z)) - ws0 * c0.z;
    v0.w = ((a0.w + a1.w) + (a2.w + a3.w)) - ws0 * c0.w;
    v1.x = ((e0.x + e1.x) + (e2.x + e3.x)) - ws1 * c1.x;
    v1.y = ((e0.y + e1.y) + (e2.y + e3.y)) - ws1 * c1.y;
    v1.z = ((e0.z + e1.z) + (e2.z + e3.z)) - ws1 * c1.z;
    v1.w = ((e0.w + e1.w) + (e2.w + e3.w)) - ws1 * c1.w;
    float ss0 = v0.x * v0.x + v0.y * v0.y + v0.z * v0.z + v0.w * v0.w;
    float ss1 = v1.x * v1.x + v1.y * v1.y + v1.z * v1.z + v1.w * v1.w;
    ss0 = warp_sum(ss0);
    ss1 = warp_sum(ss1);
    __shared__ float sm[2][4];
    if ((t & 31) == 0) { sm[0][t >> 5] = ss0; sm[1][t >> 5] = ss1; }
    __syncthreads();
    const float tot0 = (sm[0][0] + sm[0][1]) + (sm[0][2] + sm[0][3]);
    const float tot1 = (sm[1][0] + sm[1][1]) + (sm[1][2] + sm[1][3]);
    const float i0 = 1.0f / fmaxf(sqrtf(tot0), EPSV);
    const float i1 = 1.0f / fmaxf(sqrtf(tot1), EPSV);
    v0.x *= i0; v0.y *= i0; v0.z *= i0; v0.w *= i0;
    v1.x *= i1; v1.y *= i1; v1.z *= i1; v1.w *= i1;
    *(float4*)(out + row0 + t * 4) = v0;
    *(float4*)(out + row1 + t * 4) = v1;
    if (t == 0) {
        g_rn[b * K_ + k0] = tot0 * i0 * i0;
        g_rn[b * K_ + k0 + 1] = tot1 * i1 * i1;
    }
}

// ============================================================================
// scale: global L2 with inline per-block rnsum; 2 float4 per thread.
// Grid 256 (16 blocks per batch), 256 threads.
// ============================================================================
__global__ __launch_bounds__(256) void k_scale(float* __restrict__ out) {
    const int t = threadIdx.x;
    const int b = blockIdx.x >> 4;               // 16 blocks per batch
    __shared__ float sm2[2];
    __shared__ float invs;
    if (t < 64) {
        float v = g_rn[b * K_ + t];
        v += __shfl_xor_sync(0xffffffffu, v, 16);
        v += __shfl_xor_sync(0xffffffffu, v, 8);
        v += __shfl_xor_sync(0xffffffffu, v, 4);
        v += __shfl_xor_sync(0xffffffffu, v, 2);
        v += __shfl_xor_sync(0xffffffffu, v, 1);
        if ((t & 31) == 0) sm2[t >> 5] = v;
    }
    const size_t gi0 = (size_t)blockIdx.x * 2048 + t * 4;
    float4 v0 = *(float4*)(out + gi0);
    float4 v1 = *(float4*)(out + gi0 + 1024);
    __syncthreads();
    if (t == 0) invs = 1.0f / fmaxf(sqrtf(sm2[0] + sm2[1]), EPSV);
    __syncthreads();
    const float inv = invs;
    v0.x *= inv; v0.y *= inv; v0.z *= inv; v0.w *= inv;
    v1.x *= inv; v1.y *= inv; v1.z *= inv; v1.w *= inv;
    *(float4*)(out + gi0) = v0;
    *(float4*)(out + gi0 + 1024) = v1;
}

// ============================================================================
extern "C" void kernel_launch(void* const* d_in, const int* in_sizes, int n_in,
                              void* d_out, int out_size) {
    const float* x = (const float*)d_in[0];
    const float* conv_w = (const float*)d_in[1];
    const float* conv_b = (const float*)d_in[2];
    const float* centers = (const float*)d_in[3];
    float* out = (float*)d_out;

    cudaFuncSetAttribute(g1_softmax, cudaFuncAttributeMaxDynamicSharedMemorySize, G1_SMEM);
    cudaFuncSetAttribute(g2_wx, cudaFuncAttributeMaxDynamicSharedMemorySize, G2_SMEM);

    g1_softmax<<<dim3(32, 16), 256, G1_SMEM>>>(x, conv_w, conv_b);
    g2_wx<<<dim3(4, 16, 4), 256, G2_SMEM>>>(x);
    k_norm1<<<dim3(32, 16), 128>>>(centers, out);
    k_scale<<<256, 256>>>(out);
}